// round 2
// baseline (speedup 1.0000x reference)
#include <cuda_runtime.h>
#include <math.h>

// Problem constants (fixed by the dataset)
#define B_    2
#define O_    8
#define C_    32      // channels per orientation (256/8)
#define H_    256
#define W_    256
#define P_    7       // OUT_SIZE
#define PI_F  3.14159265358979323846f

// Scratch: features transposed to (B, O, H, W, C) with C contiguous.
// 2*8*256*256*32 floats = 128 MiB (static __device__ per harness rules).
__device__ float g_feats_t[(size_t)B_ * O_ * H_ * W_ * C_];

// ---------------------------------------------------------------------------
// Kernel 1: transpose (B, C*O, H, W) -> (B*O, H, W, C)
// Block (32,32): tx indexes w on load (coalesced), c on store (coalesced).
// ---------------------------------------------------------------------------
__global__ void transpose_feats_kernel(const float* __restrict__ f) {
    __shared__ float tile[32][33];
    const int tx = threadIdx.x;
    const int ty = threadIdx.y;
    const int w0 = blockIdx.x << 5;     // w tile base
    const int h  = blockIdx.y;
    const int bo = blockIdx.z;          // b*8 + o
    const int b  = bo >> 3;
    const int o  = bo & 7;

    // Read: channel ctot = ty*8 + o, pixel (h, w0+tx). Coalesced in tx (=w).
    const int ctot = (ty << 3) + o;
    tile[ty][tx] = f[(((size_t)(b * 256 + ctot) * H_ + h) * W_) + w0 + tx];
    __syncthreads();

    // Write: c = tx (contiguous), w = w0+ty. Coalesced in tx (=c).
    g_feats_t[(((size_t)bo * (H_ * W_) + (size_t)h * W_ + w0 + ty) << 5) + tx] =
        tile[tx][ty];
}

// ---------------------------------------------------------------------------
// Kernel 2: rotated RoI align.
// Grid: (py=7, o=8, roi=Rn). Block: 224 threads = 7 warps.
// Warp w handles px = w; lane = channel c (0..31).
// All coordinate math is lane-redundant; every corner gather is one
// coalesced 128B warp load from the channel-contiguous scratch.
// ---------------------------------------------------------------------------
__global__ void riroi_align_kernel(const float* __restrict__ rois,
                                   float* __restrict__ out) {
    const int py = blockIdx.x;             // 0..6
    const int o  = blockIdx.y;             // 0..7
    const int r  = blockIdx.z;             // roi index
    const int px = threadIdx.x >> 5;       // warp id = pooled x
    const int c  = threadIdx.x & 31;       // lane = channel

    const float* roi = rois + (size_t)r * 6;
    const int   b   = (int)roi[0];
    const float cw  = roi[1] * 0.125f;
    const float ch  = roi[2] * 0.125f;
    const float rw  = fmaxf(roi[3] * 0.125f, 1.0f);
    const float rh  = fmaxf(roi[4] * 0.125f, 1.0f);
    const float th  = roi[5];

    // orientation blend
    const float ind_f     = th * (O_ / (2.0f * PI_F));
    const float ind_floor = floorf(ind_f);
    const float lv        = ind_f - ind_floor;   // weight for plane+1
    const float rv        = 1.0f - lv;           // weight for plane
    const int   ind       = ((int)ind_floor) & 7;      // &7 == mod 8 (also for neg)
    const int   rot0      = (o - ind + 8) & 7;
    const int   rot1      = (rot0 + 1) & 7;

    const float ct = cosf(th);
    const float st = sinf(th);
    const float bin_h = rh * (1.0f / 7.0f);
    const float bin_w = rw * (1.0f / 7.0f);

    const float* base0 = g_feats_t + (((size_t)(b * O_ + rot0) * (H_ * W_)) << 5);
    const float* base1 = g_feats_t + (((size_t)(b * O_ + rot1) * (H_ * W_)) << 5);

    float acc = 0.0f;

#pragma unroll
    for (int gy = 0; gy < 2; ++gy) {
        const float yy = -rh * 0.5f + ((float)py + (gy + 0.5f) * 0.5f) * bin_h;
#pragma unroll
        for (int gx = 0; gx < 2; ++gx) {
            const float xx = -rw * 0.5f + ((float)px + (gx + 0.5f) * 0.5f) * bin_w;
            const float x = xx * ct - yy * st + cw;
            const float y = xx * st + yy * ct + ch;

            if (y > -1.0f && y < (float)H_ && x > -1.0f && x < (float)W_) {
                const float yc = fmaxf(y, 0.0f);
                const float xc = fmaxf(x, 0.0f);
                int yl = (int)yc;
                int xl = (int)xc;
                int yh, xh;
                float ly, lx;
                if (yl >= H_ - 1) { yl = H_ - 1; yh = H_ - 1; ly = 0.0f; }
                else              { yh = yl + 1; ly = yc - (float)yl; }
                if (xl >= W_ - 1) { xl = W_ - 1; xh = W_ - 1; lx = 0.0f; }
                else              { xh = xl + 1; lx = xc - (float)xl; }

                const float hy = 1.0f - ly, hx = 1.0f - lx;
                const float w00 = hy * hx, w01 = hy * lx;
                const float w10 = ly * hx, w11 = ly * lx;

                const int o00 = ((yl * W_ + xl) << 5) + c;
                const int o01 = ((yl * W_ + xh) << 5) + c;
                const int o10 = ((yh * W_ + xl) << 5) + c;
                const int o11 = ((yh * W_ + xh) << 5) + c;

                const float s0 = w00 * base0[o00] + w01 * base0[o01] +
                                 w10 * base0[o10] + w11 * base0[o11];
                const float s1 = w00 * base1[o00] + w01 * base1[o01] +
                                 w10 * base1[o10] + w11 * base1[o11];
                acc += rv * s0 + lv * s1;
            }
        }
    }

    // out[r, c*8 + o, py, px], channel-major layout (Rn, 256, 7, 7)
    out[(((size_t)r * 256) + (c << 3) + o) * 49 + py * 7 + px] = acc * 0.25f;
}

// ---------------------------------------------------------------------------
extern "C" void kernel_launch(void* const* d_in, const int* in_sizes, int n_in,
                              void* d_out, int out_size) {
    const float* features = (const float*)d_in[0];
    const float* rois     = (const float*)d_in[1];
    float*       out      = (float*)d_out;

    const int Rn = in_sizes[1] / 6;

    // 1) Channel-transpose features into scratch (C contiguous per pixel).
    transpose_feats_kernel<<<dim3(W_ / 32, H_, B_ * O_), dim3(32, 32)>>>(features);

    // 2) Rotated RoI align, one warp per (roi, o, py, px), lane = channel.
    riroi_align_kernel<<<dim3(P_, O_, Rn), 224>>>(rois, out);
}

// round 3
// speedup vs baseline: 1.5160x; 1.5160x over previous
#include <cuda_runtime.h>
#include <math.h>

// Problem constants (fixed by the dataset)
#define B_    2
#define O_    8
#define C_    32      // channels per orientation (256/8)
#define H_    256
#define W_    256
#define P_    7       // OUT_SIZE
#define PI_F  3.14159265358979323846f

// Scratch: features transposed to (B, O, H, W, C) with C contiguous.
// 2*8*256*256*32 floats = 128 MiB.
__device__ float g_feats_t[(size_t)B_ * O_ * H_ * W_ * C_];

// ---------------------------------------------------------------------------
// Kernel 1: transpose (B, C*O, H, W) -> (B*O, H, W, C), vectorized.
// Block = 256 threads handles one (bo, h) row: 32 channels x 256 w.
// Load:  8x LDG.128 per thread (coalesced along w, per-channel rows).
// Store: 8x STG.128 per thread (fully contiguous 512B per warp).
// Smem tile pitch 257 (== 1 mod 32) -> conflict-free scalar LDS in write phase.
// ---------------------------------------------------------------------------
__global__ void transpose_feats_kernel(const float* __restrict__ f) {
    __shared__ float tile[32][257];
    const int tid = threadIdx.x;
    const int h   = blockIdx.x;
    const int bo  = blockIdx.y;          // b*8 + o
    const int b   = bo >> 3;
    const int o   = bo & 7;

    const float4* src = (const float4*)f;
#pragma unroll
    for (int i = 0; i < 8; ++i) {
        const int idx = (i << 8) + tid;  // 0..2047
        const int cc  = idx >> 6;        // channel 0..31
        const int q   = idx & 63;        // float4 index within row
        const float4 v =
            src[(((size_t)((b << 8) + (cc << 3) + o) << 8) + h) * 64 + q];
        const int w4 = q << 2;
        tile[cc][w4 + 0] = v.x;
        tile[cc][w4 + 1] = v.y;
        tile[cc][w4 + 2] = v.z;
        tile[cc][w4 + 3] = v.w;
    }
    __syncthreads();

    float4* dst = (float4*)(g_feats_t + (((size_t)bo << 16) + (h << 8)) * 32);
#pragma unroll
    for (int i = 0; i < 8; ++i) {
        const int j4 = (i << 8) + tid;   // output float4 index 0..2047
        const int w  = j4 >> 3;
        const int c0 = (j4 & 7) << 2;
        float4 v;
        v.x = tile[c0 + 0][w];
        v.y = tile[c0 + 1][w];
        v.z = tile[c0 + 2][w];
        v.w = tile[c0 + 3][w];
        dst[j4] = v;
    }
}

// ---------------------------------------------------------------------------
// Kernel 2: rotated RoI align with orientation-plane sharing.
// Grid (py=7, roi). Block 256 threads = 8 warps.
// Warp p computes the bilinear samples of orientation-plane p ONCE
// (4 samples x 7 px, lane = channel, every gather a coalesced 128B load),
// then all 8 orientation outputs are blended via a smem exchange.
// This halves gather traffic vs. per-(o,plane) gathering.
// ---------------------------------------------------------------------------
__global__ void riroi_align_kernel(const float* __restrict__ rois,
                                   float* __restrict__ out) {
    const int py = blockIdx.x;            // 0..6
    const int r  = blockIdx.y;            // roi index
    const int p  = threadIdx.x >> 5;      // warp id = plane 0..7
    const int c  = threadIdx.x & 31;      // lane = channel

    __shared__ float sm[8][7][32];        // plane-major bilinear accumulators
    __shared__ float sout[256][7];        // ctot-major staged output

    const float* roi = rois + r * 6;
    const int   b  = (int)roi[0];
    const float cw = roi[1] * 0.125f;
    const float ch = roi[2] * 0.125f;
    const float rw = fmaxf(roi[3] * 0.125f, 1.0f);
    const float rh = fmaxf(roi[4] * 0.125f, 1.0f);
    const float th = roi[5];

    const float ind_f     = th * (O_ / (2.0f * PI_F));
    const float ind_floor = floorf(ind_f);
    const float lv        = ind_f - ind_floor;   // weight for plane rot0+1
    const float rv        = 1.0f - lv;           // weight for plane rot0
    const int   ind       = ((int)ind_floor) & 7;

    const float ct = cosf(th);
    const float st = sinf(th);
    const float bin_h = rh * (1.0f / 7.0f);
    const float bin_w = rw * (1.0f / 7.0f);

    const float* base = g_feats_t + (((size_t)(b * O_ + p)) << 21); // *65536*32

    float acc[7];
#pragma unroll
    for (int i = 0; i < 7; ++i) acc[i] = 0.0f;

#pragma unroll
    for (int s = 0; s < 4; ++s) {
        const float gy  = ((s >> 1) + 0.5f) * 0.5f;
        const float gx  = ((s & 1)  + 0.5f) * 0.5f;
        const float yy  = fmaf((float)py + gy, bin_h, -rh * 0.5f);
        const float xx0 = fmaf(gx, bin_w, -rw * 0.5f);
        const float xb  = xx0 * ct - yy * st + cw;
        const float yb  = xx0 * st + yy * ct + ch;
        const float dx  = bin_w * ct;
        const float dy  = bin_w * st;

#pragma unroll
        for (int px = 0; px < 7; ++px) {
            const float x = fmaf((float)px, dx, xb);
            const float y = fmaf((float)px, dy, yb);
            if (y > -1.0f && y < (float)H_ && x > -1.0f && x < (float)W_) {
                const float yc = fmaxf(y, 0.0f);
                const float xc = fmaxf(x, 0.0f);
                int yl = (int)yc;
                int xl = (int)xc;
                int yh, xh;
                float ly, lx;
                if (yl >= H_ - 1) { yl = H_ - 1; yh = H_ - 1; ly = 0.0f; }
                else              { yh = yl + 1; ly = yc - (float)yl; }
                if (xl >= W_ - 1) { xl = W_ - 1; xh = W_ - 1; lx = 0.0f; }
                else              { xh = xl + 1; lx = xc - (float)xl; }

                const float hy = 1.0f - ly, hx = 1.0f - lx;
                const int i00 = ((yl * W_ + xl) << 5) + c;
                const int i01 = ((yl * W_ + xh) << 5) + c;
                const int i10 = ((yh * W_ + xl) << 5) + c;
                const int i11 = ((yh * W_ + xh) << 5) + c;

                acc[px] += (hy * hx) * base[i00] + (hy * lx) * base[i01] +
                           (ly * hx) * base[i10] + (ly * lx) * base[i11];
            }
        }
    }

#pragma unroll
    for (int px = 0; px < 7; ++px) sm[p][px][c] = acc[px];
    __syncthreads();

    // Orientation blend: warp p produces orientation o = p.
    const int rot0 = (p - ind) & 7;
    const int rot1 = (rot0 + 1) & 7;
#pragma unroll
    for (int px = 0; px < 7; ++px) {
        sout[(c << 3) + p][px] =
            0.25f * (rv * sm[rot0][px][c] + lv * sm[rot1][px][c]);
    }
    __syncthreads();

    // Coalesced-ish epilogue: thread = ctot writes 7 contiguous floats.
    float* dst = out + ((size_t)r * 256 + threadIdx.x) * 49 + py * 7;
#pragma unroll
    for (int i = 0; i < 7; ++i) dst[i] = sout[threadIdx.x][i];
}

// ---------------------------------------------------------------------------
extern "C" void kernel_launch(void* const* d_in, const int* in_sizes, int n_in,
                              void* d_out, int out_size) {
    const float* features = (const float*)d_in[0];
    const float* rois     = (const float*)d_in[1];
    float*       out      = (float*)d_out;

    const int Rn = in_sizes[1] / 6;

    transpose_feats_kernel<<<dim3(H_, B_ * O_), 256>>>(features);
    riroi_align_kernel<<<dim3(P_, Rn), 256>>>(rois, out);
}

// round 4
// speedup vs baseline: 2.0787x; 1.3712x over previous
#include <cuda_runtime.h>
#include <math.h>

// Problem constants (fixed by the dataset)
#define B_    2
#define O_    8
#define C_    32      // channels per orientation (256/8)
#define H_    256
#define W_    256
#define P_    7       // OUT_SIZE
#define PI_F  3.14159265358979323846f

// Scratch: features transposed to (B, O, H, W, C) with C contiguous. 128 MiB.
__device__ float g_feats_t[(size_t)B_ * O_ * H_ * W_ * C_];

// ---------------------------------------------------------------------------
// Kernel 1: transpose (B, C*O, H, W) -> (B*O, H, W, C), vectorized.
// (unchanged: ~5.7 TB/s effective, near the memory cap)
// ---------------------------------------------------------------------------
__global__ void transpose_feats_kernel(const float* __restrict__ f) {
    __shared__ float tile[32][257];
    const int tid = threadIdx.x;
    const int h   = blockIdx.x;
    const int bo  = blockIdx.y;          // b*8 + o
    const int b   = bo >> 3;
    const int o   = bo & 7;

    const float4* src = (const float4*)f;
#pragma unroll
    for (int i = 0; i < 8; ++i) {
        const int idx = (i << 8) + tid;  // 0..2047
        const int cc  = idx >> 6;        // channel 0..31
        const int q   = idx & 63;        // float4 index within row
        const float4 v =
            src[(((size_t)((b << 8) + (cc << 3) + o) << 8) + h) * 64 + q];
        const int w4 = q << 2;
        tile[cc][w4 + 0] = v.x;
        tile[cc][w4 + 1] = v.y;
        tile[cc][w4 + 2] = v.z;
        tile[cc][w4 + 3] = v.w;
    }
    __syncthreads();

    float4* dst = (float4*)(g_feats_t + (((size_t)bo << 16) + (h << 8)) * 32);
#pragma unroll
    for (int i = 0; i < 8; ++i) {
        const int j4 = (i << 8) + tid;   // output float4 index 0..2047
        const int w  = j4 >> 3;
        const int c0 = (j4 & 7) << 2;
        float4 v;
        v.x = tile[c0 + 0][w];
        v.y = tile[c0 + 1][w];
        v.z = tile[c0 + 2][w];
        v.w = tile[c0 + 3][w];
        dst[j4] = v;
    }
}

// ---------------------------------------------------------------------------
// Kernel 2: rotated RoI align, wide-gather version.
// Grid (py=7, roi). Block 256 = 8 warps; warp = orientation plane p.
// Lane = (s, cg): s = lane>>3 is the sample (2x2 grid), cg = lane&7 is the
// channel group (float4 -> 4 channels). Per px a warp issues 4 LDG.128
// (one per bilinear corner, 4 sample-addresses x 8-lane 128B segments each).
// Sample-sum is folded at the end with shfl_xor(8)/shfl_xor(16).
// ---------------------------------------------------------------------------
__global__ void riroi_align_kernel(const float* __restrict__ rois,
                                   float* __restrict__ out) {
    const int py   = blockIdx.x;           // 0..6
    const int r    = blockIdx.y;           // roi index
    const int tid  = threadIdx.x;
    const int p    = tid >> 5;              // warp id = plane 0..7
    const int lane = tid & 31;
    const int s    = lane >> 3;              // sample 0..3
    const int cg   = lane & 7;               // channel group 0..7 (x4 channels)

    __shared__ float sm[8][7][33];           // [plane][px][channel(+pad)]

    const float* roi = rois + r * 6;
    const int   b  = (int)roi[0];
    const float cw = roi[1] * 0.125f;
    const float ch = roi[2] * 0.125f;
    const float rw = fmaxf(roi[3] * 0.125f, 1.0f);
    const float rh = fmaxf(roi[4] * 0.125f, 1.0f);
    const float th = roi[5];

    const float ind_f     = th * (O_ / (2.0f * PI_F));
    const float ind_floor = floorf(ind_f);
    const float lv        = ind_f - ind_floor;
    const float rv        = 1.0f - lv;
    const int   ind       = ((int)ind_floor) & 7;

    const float ct = cosf(th);
    const float st = sinf(th);
    const float bin_h = rh * (1.0f / 7.0f);
    const float bin_w = rw * (1.0f / 7.0f);

    // this lane's sample offsets within the bin (2x2 grid)
    const float gy = ((s >> 1) + 0.5f) * 0.5f;
    const float gx = ((s & 1)  + 0.5f) * 0.5f;

    const float yy  = fmaf((float)py + gy, bin_h, -rh * 0.5f);
    const float xx0 = fmaf(gx, bin_w, -rw * 0.5f);
    const float xb  = xx0 * ct - yy * st + cw;
    const float yb  = xx0 * st + yy * ct + ch;
    const float dx  = bin_w * ct;
    const float dy  = bin_w * st;

    // plane base as float4*: pixel stride = 8 float4
    const float4* base4 =
        (const float4*)g_feats_t + (((size_t)(b * O_ + p)) << 19) + cg;

    float4 acc[7];
#pragma unroll
    for (int i = 0; i < 7; ++i) acc[i] = make_float4(0.f, 0.f, 0.f, 0.f);

#pragma unroll
    for (int px = 0; px < 7; ++px) {
        const float x = fmaf((float)px, dx, xb);
        const float y = fmaf((float)px, dy, yb);
        if (y > -1.0f && y < (float)H_ && x > -1.0f && x < (float)W_) {
            const float yc = fmaxf(y, 0.0f);
            const float xc = fmaxf(x, 0.0f);
            int yl = (int)yc;
            int xl = (int)xc;
            int yh, xh;
            float ly, lx;
            if (yl >= H_ - 1) { yl = H_ - 1; yh = H_ - 1; ly = 0.0f; }
            else              { yh = yl + 1; ly = yc - (float)yl; }
            if (xl >= W_ - 1) { xl = W_ - 1; xh = W_ - 1; lx = 0.0f; }
            else              { xh = xl + 1; lx = xc - (float)xl; }

            const float hy = 1.0f - ly, hx = 1.0f - lx;
            const float w00 = hy * hx, w01 = hy * lx;
            const float w10 = ly * hx, w11 = ly * lx;

            const float4 v00 = base4[((yl << 8) + xl) << 3];
            const float4 v01 = base4[((yl << 8) + xh) << 3];
            const float4 v10 = base4[((yh << 8) + xl) << 3];
            const float4 v11 = base4[((yh << 8) + xh) << 3];

            float4 a = acc[px];
            a.x = fmaf(w00, v00.x, fmaf(w01, v01.x, fmaf(w10, v10.x, fmaf(w11, v11.x, a.x))));
            a.y = fmaf(w00, v00.y, fmaf(w01, v01.y, fmaf(w10, v10.y, fmaf(w11, v11.y, a.y))));
            a.z = fmaf(w00, v00.z, fmaf(w01, v01.z, fmaf(w10, v10.z, fmaf(w11, v11.z, a.z))));
            a.w = fmaf(w00, v00.w, fmaf(w01, v01.w, fmaf(w10, v10.w, fmaf(w11, v11.w, a.w))));
            acc[px] = a;
        }
    }

    // Fold the 4 samples (lane groups of 8) with butterfly shuffles,
    // then lanes of sample 0 store the 32-channel result for this plane.
#pragma unroll
    for (int px = 0; px < 7; ++px) {
        float4 a = acc[px];
        a.x += __shfl_xor_sync(0xffffffffu, a.x, 8);
        a.y += __shfl_xor_sync(0xffffffffu, a.y, 8);
        a.z += __shfl_xor_sync(0xffffffffu, a.z, 8);
        a.w += __shfl_xor_sync(0xffffffffu, a.w, 8);
        a.x += __shfl_xor_sync(0xffffffffu, a.x, 16);
        a.y += __shfl_xor_sync(0xffffffffu, a.y, 16);
        a.z += __shfl_xor_sync(0xffffffffu, a.z, 16);
        a.w += __shfl_xor_sync(0xffffffffu, a.w, 16);
        if (s == 0) {
            float* row = &sm[p][px][cg << 2];
            row[0] = a.x; row[1] = a.y; row[2] = a.z; row[3] = a.w;
        }
    }
    __syncthreads();

    // Blend phase: thread = ctot = c*8 + o. Read the two rotated planes,
    // write 7 contiguous floats per thread.
    const int c_t  = tid >> 3;               // channel 0..31
    const int oo   = tid & 7;                // orientation 0..7
    const int rot0 = (oo - ind) & 7;
    const int rot1 = (rot0 + 1) & 7;

    float* dst = out + ((size_t)r * 256 + tid) * 49 + py * 7;
#pragma unroll
    for (int px = 0; px < 7; ++px) {
        dst[px] = 0.25f * (rv * sm[rot0][px][c_t] + lv * sm[rot1][px][c_t]);
    }
}

// ---------------------------------------------------------------------------
extern "C" void kernel_launch(void* const* d_in, const int* in_sizes, int n_in,
                              void* d_out, int out_size) {
    const float* features = (const float*)d_in[0];
    const float* rois     = (const float*)d_in[1];
    float*       out      = (float*)d_out;

    const int Rn = in_sizes[1] / 6;

    transpose_feats_kernel<<<dim3(H_, B_ * O_), 256>>>(features);
    riroi_align_kernel<<<dim3(P_, Rn), 256>>>(rois, out);
}

// round 14
// speedup vs baseline: 2.4526x; 1.1799x over previous
#include <cuda_runtime.h>
#include <cuda_fp16.h>
#include <math.h>

// Problem constants (fixed by the dataset)
#define B_    2
#define O_    8
#define C_    32      // channels per orientation (256/8)
#define H_    256
#define W_    256
#define P_    7       // OUT_SIZE
#define PI_F  3.14159265358979323846f

// Scratch: features transposed to (B, O, H, W, C), C contiguous, fp16. 64 MiB.
// Fits in L2 (126 MB) -> main-kernel gathers become L2-resident.
__device__ __half g_feats_t[(size_t)B_ * O_ * H_ * W_ * C_];

// bit-cast helper (must precede first use)
static __device__ __forceinline__ unsigned int half2_as_uint(__half2 h) {
    return *reinterpret_cast<unsigned int*>(&h);
}

// ---------------------------------------------------------------------------
// Kernel 1: transpose (B, C*O, H, W) fp32 -> (B*O, H, W, C) fp16.
// Block = 256 threads per (bo, h) row. LDG.128 reads, 8B stores (256B/warp).
// ---------------------------------------------------------------------------
__global__ void transpose_feats_kernel(const float* __restrict__ f) {
    __shared__ float tile[32][257];
    const int tid = threadIdx.x;
    const int h   = blockIdx.x;
    const int bo  = blockIdx.y;          // b*8 + o
    const int b   = bo >> 3;
    const int o   = bo & 7;

    const float4* src = (const float4*)f;
#pragma unroll
    for (int i = 0; i < 8; ++i) {
        const int idx = (i << 8) + tid;  // 0..2047
        const int cc  = idx >> 6;        // channel 0..31
        const int q   = idx & 63;        // float4 index within row
        const float4 v =
            src[(((size_t)((b << 8) + (cc << 3) + o) << 8) + h) * 64 + q];
        const int w4 = q << 2;
        tile[cc][w4 + 0] = v.x;
        tile[cc][w4 + 1] = v.y;
        tile[cc][w4 + 2] = v.z;
        tile[cc][w4 + 3] = v.w;
    }
    __syncthreads();

    // Output row base in halves: (bo*65536 + h*256) * 32; as uint2 (4 halves): *8
    uint2* dst = (uint2*)g_feats_t + (((size_t)bo << 16) + (h << 8)) * 8;
#pragma unroll
    for (int i = 0; i < 8; ++i) {
        const int j4 = (i << 8) + tid;   // half4 index 0..2047
        const int w  = j4 >> 3;
        const int c0 = (j4 & 7) << 2;
        const __half2 lo = __floats2half2_rn(tile[c0 + 0][w], tile[c0 + 1][w]);
        const __half2 hi = __floats2half2_rn(tile[c0 + 2][w], tile[c0 + 3][w]);
        uint2 v;
        v.x = half2_as_uint(lo);
        v.y = half2_as_uint(hi);
        dst[j4] = v;
    }
}

// ---------------------------------------------------------------------------
// Kernel 2: rotated RoI align, fp16 wide-gather version.
// Grid (py=7, roi). Block 256 = 8 warps; warp = orientation plane p.
// Lane = (s, cg): s = sample 0..3 (2x2 grid), cg = channel group (4 halves).
// Per px: 4 LDG.64 per warp (one per bilinear corner). fp32 accumulation.
// ---------------------------------------------------------------------------
__global__ void riroi_align_kernel(const float* __restrict__ rois,
                                   float* __restrict__ out) {
    const int py   = blockIdx.x;           // 0..6
    const int r    = blockIdx.y;           // roi index
    const int tid  = threadIdx.x;
    const int p    = tid >> 5;              // warp id = plane 0..7
    const int lane = tid & 31;
    const int s    = lane >> 3;              // sample 0..3
    const int cg   = lane & 7;               // channel group 0..7 (x4 channels)

    __shared__ float sm[8][7][33];           // [plane][px][channel(+pad)]

    const float* roi = rois + r * 6;
    const int   b  = (int)roi[0];
    const float cw = roi[1] * 0.125f;
    const float ch = roi[2] * 0.125f;
    const float rw = fmaxf(roi[3] * 0.125f, 1.0f);
    const float rh = fmaxf(roi[4] * 0.125f, 1.0f);
    const float th = roi[5];

    const float ind_f     = th * (O_ / (2.0f * PI_F));
    const float ind_floor = floorf(ind_f);
    const float lv        = ind_f - ind_floor;
    const float rv        = 1.0f - lv;
    const int   ind       = ((int)ind_floor) & 7;

    const float ct = cosf(th);
    const float st = sinf(th);
    const float bin_h = rh * (1.0f / 7.0f);
    const float bin_w = rw * (1.0f / 7.0f);

    const float gy = ((s >> 1) + 0.5f) * 0.5f;
    const float gx = ((s & 1)  + 0.5f) * 0.5f;

    const float yy  = fmaf((float)py + gy, bin_h, -rh * 0.5f);
    const float xx0 = fmaf(gx, bin_w, -rw * 0.5f);
    const float xb  = xx0 * ct - yy * st + cw;
    const float yb  = xx0 * st + yy * ct + ch;
    const float dx  = bin_w * ct;
    const float dy  = bin_w * st;

    // plane base as uint2* (4 halves); pixel stride = 8 uint2
    const uint2* base2 =
        (const uint2*)g_feats_t + (((size_t)(b * O_ + p)) << 19) + cg;

    float4 acc[7];
#pragma unroll
    for (int i = 0; i < 7; ++i) acc[i] = make_float4(0.f, 0.f, 0.f, 0.f);

#pragma unroll
    for (int px = 0; px < 7; ++px) {
        const float x = fmaf((float)px, dx, xb);
        const float y = fmaf((float)px, dy, yb);
        if (y > -1.0f && y < (float)H_ && x > -1.0f && x < (float)W_) {
            const float yc = fmaxf(y, 0.0f);
            const float xc = fmaxf(x, 0.0f);
            int yl = (int)yc;
            int xl = (int)xc;
            int yh, xh;
            float ly, lx;
            if (yl >= H_ - 1) { yl = H_ - 1; yh = H_ - 1; ly = 0.0f; }
            else              { yh = yl + 1; ly = yc - (float)yl; }
            if (xl >= W_ - 1) { xl = W_ - 1; xh = W_ - 1; lx = 0.0f; }
            else              { xh = xl + 1; lx = xc - (float)xl; }

            const float hy = 1.0f - ly, hx = 1.0f - lx;
            const float w00 = hy * hx, w01 = hy * lx;
            const float w10 = ly * hx, w11 = ly * lx;

            const uint2 u00 = base2[((yl << 8) + xl) << 3];
            const uint2 u01 = base2[((yl << 8) + xh) << 3];
            const uint2 u10 = base2[((yh << 8) + xl) << 3];
            const uint2 u11 = base2[((yh << 8) + xh) << 3];

            const float2 a00 = __half22float2(*(const __half2*)&u00.x);
            const float2 b00 = __half22float2(*(const __half2*)&u00.y);
            const float2 a01 = __half22float2(*(const __half2*)&u01.x);
            const float2 b01 = __half22float2(*(const __half2*)&u01.y);
            const float2 a10 = __half22float2(*(const __half2*)&u10.x);
            const float2 b10 = __half22float2(*(const __half2*)&u10.y);
            const float2 a11 = __half22float2(*(const __half2*)&u11.x);
            const float2 b11 = __half22float2(*(const __half2*)&u11.y);

            float4 a = acc[px];
            a.x = fmaf(w00, a00.x, fmaf(w01, a01.x, fmaf(w10, a10.x, fmaf(w11, a11.x, a.x))));
            a.y = fmaf(w00, a00.y, fmaf(w01, a01.y, fmaf(w10, a10.y, fmaf(w11, a11.y, a.y))));
            a.z = fmaf(w00, b00.x, fmaf(w01, b01.x, fmaf(w10, b10.x, fmaf(w11, b11.x, a.z))));
            a.w = fmaf(w00, b00.y, fmaf(w01, b01.y, fmaf(w10, b10.y, fmaf(w11, b11.y, a.w))));
            acc[px] = a;
        }
    }

    // Fold the 4 samples with butterfly shuffles; sample-0 lanes store.
#pragma unroll
    for (int px = 0; px < 7; ++px) {
        float4 a = acc[px];
        a.x += __shfl_xor_sync(0xffffffffu, a.x, 8);
        a.y += __shfl_xor_sync(0xffffffffu, a.y, 8);
        a.z += __shfl_xor_sync(0xffffffffu, a.z, 8);
        a.w += __shfl_xor_sync(0xffffffffu, a.w, 8);
        a.x += __shfl_xor_sync(0xffffffffu, a.x, 16);
        a.y += __shfl_xor_sync(0xffffffffu, a.y, 16);
        a.z += __shfl_xor_sync(0xffffffffu, a.z, 16);
        a.w += __shfl_xor_sync(0xffffffffu, a.w, 16);
        if (s == 0) {
            float* row = &sm[p][px][cg << 2];
            row[0] = a.x; row[1] = a.y; row[2] = a.z; row[3] = a.w;
        }
    }
    __syncthreads();

    // Blend phase: thread = ctot = c*8 + o; write 7 contiguous floats.
    const int c_t  = tid >> 3;               // channel 0..31
    const int oo   = tid & 7;                // orientation 0..7
    const int rot0 = (oo - ind) & 7;
    const int rot1 = (rot0 + 1) & 7;

    float* dst = out + ((size_t)r * 256 + tid) * 49 + py * 7;
#pragma unroll
    for (int px = 0; px < 7; ++px) {
        dst[px] = 0.25f * (rv * sm[rot0][px][c_t] + lv * sm[rot1][px][c_t]);
    }
}

// ---------------------------------------------------------------------------
extern "C" void kernel_launch(void* const* d_in, const int* in_sizes, int n_in,
                              void* d_out, int out_size) {
    const float* features = (const float*)d_in[0];
    const float* rois     = (const float*)d_in[1];
    float*       out      = (float*)d_out;

    const int Rn = in_sizes[1] / 6;

    transpose_feats_kernel<<<dim3(H_, B_ * O_), 256>>>(features);
    riroi_align_kernel<<<dim3(P_, Rn), 256>>>(rois, out);
}

// round 15
// speedup vs baseline: 2.5416x; 1.0363x over previous
#include <cuda_runtime.h>
#include <cuda_fp16.h>
#include <math.h>

// Problem constants (fixed by the dataset)
#define B_    2
#define O_    8
#define C_    32      // channels per orientation (256/8)
#define H_    256
#define W_    256
#define P_    7       // OUT_SIZE
#define PI_F  3.14159265358979323846f

// Scratch: features transposed to (B, O, H, W, C), C contiguous, fp16. 64 MiB.
// Fits in L2 (126 MB) -> main-kernel gathers are L2-resident.
__device__ __half g_feats_t[(size_t)B_ * O_ * H_ * W_ * C_];

// bit-cast helper (must precede first use)
static __device__ __forceinline__ unsigned int half2_as_uint(__half2 h) {
    return *reinterpret_cast<unsigned int*>(&h);
}

// ---------------------------------------------------------------------------
// Kernel 1: transpose (B, C*O, H, W) fp32 -> (B*O, H, W, C) fp16.
// ---------------------------------------------------------------------------
__global__ void transpose_feats_kernel(const float* __restrict__ f) {
    __shared__ float tile[32][257];
    const int tid = threadIdx.x;
    const int h   = blockIdx.x;
    const int bo  = blockIdx.y;          // b*8 + o
    const int b   = bo >> 3;
    const int o   = bo & 7;

    const float4* src = (const float4*)f;
#pragma unroll
    for (int i = 0; i < 8; ++i) {
        const int idx = (i << 8) + tid;  // 0..2047
        const int cc  = idx >> 6;        // channel 0..31
        const int q   = idx & 63;        // float4 index within row
        const float4 v =
            src[(((size_t)((b << 8) + (cc << 3) + o) << 8) + h) * 64 + q];
        const int w4 = q << 2;
        tile[cc][w4 + 0] = v.x;
        tile[cc][w4 + 1] = v.y;
        tile[cc][w4 + 2] = v.z;
        tile[cc][w4 + 3] = v.w;
    }
    __syncthreads();

    uint2* dst = (uint2*)g_feats_t + (((size_t)bo << 16) + (h << 8)) * 8;
#pragma unroll
    for (int i = 0; i < 8; ++i) {
        const int j4 = (i << 8) + tid;   // half4 index 0..2047
        const int w  = j4 >> 3;
        const int c0 = (j4 & 7) << 2;
        const __half2 lo = __floats2half2_rn(tile[c0 + 0][w], tile[c0 + 1][w]);
        const __half2 hi = __floats2half2_rn(tile[c0 + 2][w], tile[c0 + 3][w]);
        uint2 v;
        v.x = half2_as_uint(lo);
        v.y = half2_as_uint(hi);
        dst[j4] = v;
    }
}

// ---------------------------------------------------------------------------
// Kernel 2: rotated RoI align, one block per roi.
// Block 256 = 8 warps; warp = orientation plane p, computes ALL 49 cells.
// Lane = (s, cg): s = sample 0..3, cg = channel group (4 halves, LDG.64).
// Per py-row: 7 float4 accumulators, sample-fold via shfl_xor, stage to smem.
// Epilogue: blend + FULLY COALESCED float4 stores over the roi's contiguous
// 50KB output block (the previous per-thread stride-49 scatter cost ~32x in
// store wavefronts).
// Dynamic smem: 8*49*33 floats = 51744 B (needs opt-in attribute).
// ---------------------------------------------------------------------------
extern __shared__ float sm_dyn[];   // [plane][cell][33]

__global__ __launch_bounds__(256, 4)
void riroi_align_kernel(const float* __restrict__ rois,
                        float* __restrict__ out) {
    const int r    = blockIdx.x;            // roi index
    const int tid  = threadIdx.x;
    const int p    = tid >> 5;               // warp id = plane 0..7
    const int lane = tid & 31;
    const int s    = lane >> 3;              // sample 0..3
    const int cg   = lane & 7;               // channel group 0..7 (x4 channels)

    const float* roi = rois + r * 6;
    const int   b  = (int)roi[0];
    const float cw = roi[1] * 0.125f;
    const float ch = roi[2] * 0.125f;
    const float rw = fmaxf(roi[3] * 0.125f, 1.0f);
    const float rh = fmaxf(roi[4] * 0.125f, 1.0f);
    const float th = roi[5];

    const float ind_f     = th * (O_ / (2.0f * PI_F));
    const float ind_floor = floorf(ind_f);
    const float lv        = ind_f - ind_floor;
    const float rv        = 1.0f - lv;
    const int   ind       = ((int)ind_floor) & 7;

    const float ct = cosf(th);
    const float st = sinf(th);
    const float bin_h = rh * (1.0f / 7.0f);
    const float bin_w = rw * (1.0f / 7.0f);

    const float gy = ((s >> 1) + 0.5f) * 0.5f;
    const float gx = ((s & 1)  + 0.5f) * 0.5f;

    const float xx0 = fmaf(gx, bin_w, -rw * 0.5f);
    const float dx  = bin_w * ct;
    const float dy  = bin_w * st;

    // plane base as uint2* (4 halves); pixel stride = 8 uint2
    const uint2* base2 =
        (const uint2*)g_feats_t + (((size_t)(b * O_ + p)) << 19) + cg;

    for (int py = 0; py < 7; ++py) {
        const float yy = fmaf((float)py + gy, bin_h, -rh * 0.5f);
        const float xb = xx0 * ct - yy * st + cw;
        const float yb = xx0 * st + yy * ct + ch;

        float4 acc[7];
#pragma unroll
        for (int i = 0; i < 7; ++i) acc[i] = make_float4(0.f, 0.f, 0.f, 0.f);

#pragma unroll
        for (int px = 0; px < 7; ++px) {
            const float x = fmaf((float)px, dx, xb);
            const float y = fmaf((float)px, dy, yb);
            if (y > -1.0f && y < (float)H_ && x > -1.0f && x < (float)W_) {
                const float yc = fmaxf(y, 0.0f);
                const float xc = fmaxf(x, 0.0f);
                int yl = (int)yc;
                int xl = (int)xc;
                int yh, xh;
                float ly, lx;
                if (yl >= H_ - 1) { yl = H_ - 1; yh = H_ - 1; ly = 0.0f; }
                else              { yh = yl + 1; ly = yc - (float)yl; }
                if (xl >= W_ - 1) { xl = W_ - 1; xh = W_ - 1; lx = 0.0f; }
                else              { xh = xl + 1; lx = xc - (float)xl; }

                const float hy = 1.0f - ly, hx = 1.0f - lx;
                const float w00 = hy * hx, w01 = hy * lx;
                const float w10 = ly * hx, w11 = ly * lx;

                const uint2 u00 = base2[((yl << 8) + xl) << 3];
                const uint2 u01 = base2[((yl << 8) + xh) << 3];
                const uint2 u10 = base2[((yh << 8) + xl) << 3];
                const uint2 u11 = base2[((yh << 8) + xh) << 3];

                const float2 a00 = __half22float2(*(const __half2*)&u00.x);
                const float2 b00 = __half22float2(*(const __half2*)&u00.y);
                const float2 a01 = __half22float2(*(const __half2*)&u01.x);
                const float2 b01 = __half22float2(*(const __half2*)&u01.y);
                const float2 a10 = __half22float2(*(const __half2*)&u10.x);
                const float2 b10 = __half22float2(*(const __half2*)&u10.y);
                const float2 a11 = __half22float2(*(const __half2*)&u11.x);
                const float2 b11 = __half22float2(*(const __half2*)&u11.y);

                float4 a = acc[px];
                a.x = fmaf(w00, a00.x, fmaf(w01, a01.x, fmaf(w10, a10.x, fmaf(w11, a11.x, a.x))));
                a.y = fmaf(w00, a00.y, fmaf(w01, a01.y, fmaf(w10, a10.y, fmaf(w11, a11.y, a.y))));
                a.z = fmaf(w00, b00.x, fmaf(w01, b01.x, fmaf(w10, b10.x, fmaf(w11, b11.x, a.z))));
                a.w = fmaf(w00, b00.y, fmaf(w01, b01.y, fmaf(w10, b10.y, fmaf(w11, b11.y, a.w))));
                acc[px] = a;
            }
        }

        // Fold 4 samples; sample-0 lanes stage this row into smem.
#pragma unroll
        for (int px = 0; px < 7; ++px) {
            float4 a = acc[px];
            a.x += __shfl_xor_sync(0xffffffffu, a.x, 8);
            a.y += __shfl_xor_sync(0xffffffffu, a.y, 8);
            a.z += __shfl_xor_sync(0xffffffffu, a.z, 8);
            a.w += __shfl_xor_sync(0xffffffffu, a.w, 8);
            a.x += __shfl_xor_sync(0xffffffffu, a.x, 16);
            a.y += __shfl_xor_sync(0xffffffffu, a.y, 16);
            a.z += __shfl_xor_sync(0xffffffffu, a.z, 16);
            a.w += __shfl_xor_sync(0xffffffffu, a.w, 16);
            if (s == 0) {
                float* row = sm_dyn + ((p * 49 + py * 7 + px) * 33) + (cg << 2);
                row[0] = a.x; row[1] = a.y; row[2] = a.z; row[3] = a.w;
            }
        }
    }
    __syncthreads();

    // Epilogue: blend two rotated planes, write the roi's 12544-float output
    // block fully coalesced as float4.
    float4* dst4 = (float4*)(out + (size_t)r * (256 * 49));
#pragma unroll 1
    for (int j = tid; j < (256 * 49) / 4; j += 256) {
        const int f0 = j << 2;
        float v[4];
#pragma unroll
        for (int e = 0; e < 4; ++e) {
            const int f    = f0 + e;
            const int ctot = f / 49;
            const int cell = f - ctot * 49;
            const int c    = ctot >> 3;
            const int oo   = ctot & 7;
            const int rot0 = (oo - ind) & 7;
            const int rot1 = (rot0 + 1) & 7;
            v[e] = 0.25f * (rv * sm_dyn[(rot0 * 49 + cell) * 33 + c] +
                            lv * sm_dyn[(rot1 * 49 + cell) * 33 + c]);
        }
        dst4[j] = make_float4(v[0], v[1], v[2], v[3]);
    }
}

// ---------------------------------------------------------------------------
extern "C" void kernel_launch(void* const* d_in, const int* in_sizes, int n_in,
                              void* d_out, int out_size) {
    const float* features = (const float*)d_in[0];
    const float* rois     = (const float*)d_in[1];
    float*       out      = (float*)d_out;

    const int Rn = in_sizes[1] / 6;
    const int smem_bytes = 8 * 49 * 33 * (int)sizeof(float);   // 51744

    cudaFuncSetAttribute(riroi_align_kernel,
                         cudaFuncAttributeMaxDynamicSharedMemorySize,
                         smem_bytes);

    transpose_feats_kernel<<<dim3(H_, B_ * O_), 256>>>(features);
    riroi_align_kernel<<<Rn, 256, smem_bytes>>>(rois, out);
}